// round 9
// baseline (speedup 1.0000x reference)
#include <cuda_runtime.h>
#include <cuda_fp16.h>
#include <cstdint>

// out[b,o] = x @ w_eff^T,  w_eff[o,i] = (sum_p coef[o,i,p]) * weights[o,i]
// Single fp16 GEMM on HMMA (m16n8k16, fp32 accum): C = fp16(x) @ fp16(w_eff)^T
// rel_err ~2.9e-4 (calibrated R6/R7), threshold 1e-3.

#define BATCH 8192
#define IN    1024
#define OUT   1024
#define PDIM  8

__device__ __half g_ahi[BATCH * IN];
__device__ __half g_bhi[OUT * IN];   // [O,I] row-major == B^T [N,K]

// ============================ fused prep kernel ============================
#define XBLKS ((BATCH * IN / 4) / 256)
#define WBLKS ((OUT * IN) / 256)

__global__ __launch_bounds__(256) void prep_kernel(
    const float* __restrict__ x,
    const float* __restrict__ coef,
    const float* __restrict__ w)
{
    if (blockIdx.x < XBLKS) {
        int idx = blockIdx.x * 256 + threadIdx.x;      // over BATCH*IN/4
        float4 v = reinterpret_cast<const float4*>(x)[idx];
        union { __half h[4]; uint2 u; } hi;
        hi.h[0] = __float2half_rn(v.x);
        hi.h[1] = __float2half_rn(v.y);
        hi.h[2] = __float2half_rn(v.z);
        hi.h[3] = __float2half_rn(v.w);
        reinterpret_cast<uint2*>(g_ahi)[idx] = hi.u;
    } else {
        int idx = (blockIdx.x - XBLKS) * 256 + threadIdx.x;   // over O*I
        const float4* c4 = reinterpret_cast<const float4*>(coef + (size_t)idx * PDIM);
        float4 a = c4[0];
        float4 b = c4[1];
        float s = (((a.x + a.y) + (a.z + a.w)) + ((b.x + b.y) + (b.z + b.w))) * w[idx];
        g_bhi[idx] = __float2half_rn(s);
    }
}

// ============================ GEMM ============================
// Block 128x128x32, 256 threads (8 warps, 4 along M x 2 along N),
// warp tile 32x64. 2 CTAs/SM (128 regs/thread cap) -> 4 warps/SMSP.
// 4-stage cp.async pipeline (issue-ahead 3), 1 syncthreads per k-iter.
#define BM 128
#define BN 128
#define BK 32
#define KITERS 32          // 1024/32
#define STAGES 4

#define ROWB 40            // halfs per smem row (80B stride, conflict-free)
#define A_STG (BM * ROWB)
#define B_STG (BN * ROWB)
#define STG   (A_STG + B_STG)
#define SMEM_BYTES (STAGES * STG * 2)   // 81,920 per CTA

__device__ __forceinline__ uint32_t smem_u32(const void* p) {
    uint32_t a;
    asm("{ .reg .u64 t; cvta.to.shared.u64 t, %1; cvt.u32.u64 %0, t; }" : "=r"(a) : "l"(p));
    return a;
}
__device__ __forceinline__ void cp16(uint32_t dst, const void* src) {
    asm volatile("cp.async.cg.shared.global [%0], [%1], 16;" :: "r"(dst), "l"(src));
}
__device__ __forceinline__ void cp_commit() {
    asm volatile("cp.async.commit_group;");
}
template <int N>
__device__ __forceinline__ void cp_wait() {
    asm volatile("cp.async.wait_group %0;" :: "n"(N));
}
__device__ __forceinline__ void ldmx4(uint32_t* r, uint32_t addr) {
    asm volatile("ldmatrix.sync.aligned.m8n8.x4.shared.b16 {%0,%1,%2,%3}, [%4];"
                 : "=r"(r[0]), "=r"(r[1]), "=r"(r[2]), "=r"(r[3]) : "r"(addr));
}
__device__ __forceinline__ void hmma(float* c, const uint32_t* a, const uint32_t* b) {
    asm volatile(
        "mma.sync.aligned.m16n8k16.row.col.f32.f16.f16.f32 "
        "{%0,%1,%2,%3}, {%4,%5,%6,%7}, {%8,%9}, {%0,%1,%2,%3};"
        : "+f"(c[0]), "+f"(c[1]), "+f"(c[2]), "+f"(c[3])
        : "r"(a[0]), "r"(a[1]), "r"(a[2]), "r"(a[3]), "r"(b[0]), "r"(b[1]));
}

__global__ __launch_bounds__(256, 2) void gemm_hmma(float* __restrict__ C)
{
    extern __shared__ __half smem[];

    const int tid = threadIdx.x;
    const int wid = tid >> 5;
    const int lid = tid & 31;
    const int warp_m = (wid & 3) * 32;     // 4 warps along M
    const int warp_n = (wid >> 2) * 64;    // 2 warps along N

    const int bm = blockIdx.y * BM;
    const int bn = blockIdx.x * BN;

    // cp.async mapping: A stage = 128 rows x 64B = 512 chunks (2/thread),
    //                   B stage = 128 rows x 64B = 512 chunks (2/thread)
    const int ld_row = tid >> 2;           // 0..63
    const int ld_seg = (tid & 3) * 8;      // half offset in row: 0,8,16,24

    uint32_t stg_base[STAGES];
#pragma unroll
    for (int s = 0; s < STAGES; s++) stg_base[s] = smem_u32(smem + s * STG);

    float acc[2][8][4];
#pragma unroll
    for (int i = 0; i < 2; i++)
#pragma unroll
        for (int j = 0; j < 8; j++)
#pragma unroll
            for (int q = 0; q < 4; q++) acc[i][j][q] = 0.f;

    // ldmatrix lane addressing (byte offsets within tile)
    const int a_lrow = warp_m + (lid & 15);
    const int a_lcol = (lid >> 4) * 16;
    const int b_lrow = warp_n + ((lid >> 4) << 3) + (lid & 7);
    const int b_lcol = ((lid >> 3) & 1) * 16;

    auto issue_tile = [&](int kt, int stage) {
        const int ko = kt * BK;
        const uint32_t ab = stg_base[stage];
        const uint32_t bb = ab + A_STG * 2;
#pragma unroll
        for (int q = 0; q < 2; q++) {
            const int row = ld_row + q * 64;
            cp16(ab + (row * ROWB + ld_seg) * 2,
                 &g_ahi[(size_t)(bm + row) * IN + ko + ld_seg]);
        }
#pragma unroll
        for (int q = 0; q < 2; q++) {
            const int row = ld_row + q * 64;
            cp16(bb + (row * ROWB + ld_seg) * 2,
                 &g_bhi[(size_t)(bn + row) * IN + ko + ld_seg]);
        }
        cp_commit();
    };

    issue_tile(0, 0);
    issue_tile(1, 1);
    issue_tile(2, 2);

    for (int kt = 0; kt < KITERS; kt++) {
        const int stage = kt % STAGES;
        cp_wait<2>();          // tile kt complete (kt+1, kt+2 may be in flight)
        __syncthreads();

        const uint32_t a_base = stg_base[stage];
        const uint32_t b_base = a_base + A_STG * 2;

#pragma unroll
        for (int h = 0; h < 2; h++) {                 // two k16 halves of BK=32
            uint32_t afrag[2][4];
#pragma unroll
            for (int mt = 0; mt < 2; mt++)
                ldmx4(afrag[mt],
                      a_base + ((a_lrow + mt * 16) * ROWB) * 2 + h * 32 + a_lcol);

            uint32_t bfrag[4][4];
#pragma unroll
            for (int nt2 = 0; nt2 < 4; nt2++)
                ldmx4(bfrag[nt2],
                      b_base + ((b_lrow + nt2 * 16) * ROWB) * 2 + h * 32 + b_lcol);

#pragma unroll
            for (int mt = 0; mt < 2; mt++)
#pragma unroll
                for (int nt2 = 0; nt2 < 4; nt2++) {
                    hmma(acc[mt][nt2 * 2 + 0], afrag[mt], &bfrag[nt2][0]);
                    hmma(acc[mt][nt2 * 2 + 1], afrag[mt], &bfrag[nt2][2]);
                }
        }

        // issue tile kt+3 into the stage consumed at iter kt-1 (all warps
        // passed this iteration's barrier). Wraparound keeps cp.async group
        // counts uniform so cp_wait<2> stays aligned.
        issue_tile((kt + 3) % KITERS, (kt + 3) % STAGES);
    }

    // epilogue
#pragma unroll
    for (int mt = 0; mt < 2; mt++) {
        const int row0 = bm + warp_m + mt * 16 + (lid >> 2);
#pragma unroll
        for (int nt = 0; nt < 8; nt++) {
            const int col = bn + warp_n + nt * 8 + 2 * (lid & 3);
            float2 v0 = {acc[mt][nt][0], acc[mt][nt][1]};
            float2 v1 = {acc[mt][nt][2], acc[mt][nt][3]};
            *reinterpret_cast<float2*>(&C[(size_t)row0 * OUT + col]) = v0;
            *reinterpret_cast<float2*>(&C[(size_t)(row0 + 8) * OUT + col]) = v1;
        }
    }
}

// ============================ launch ============================
extern "C" void kernel_launch(void* const* d_in, const int* in_sizes, int n_in,
                              void* d_out, int out_size)
{
    const float* x    = (const float*)d_in[0];   // [8192,1024]
    const float* coef = (const float*)d_in[1];   // [1024,1024,8]
    const float* w    = (const float*)d_in[2];   // [1024,1024]
    float* out        = (float*)d_out;           // [8192,1024]
    (void)in_sizes; (void)n_in; (void)out_size;

    static int attr_set = 0;
    if (!attr_set) {
        cudaFuncSetAttribute(gemm_hmma,
                             cudaFuncAttributeMaxDynamicSharedMemorySize, SMEM_BYTES);
        attr_set = 1;
    }

    prep_kernel<<<XBLKS + WBLKS, 256>>>(x, coef, w);

    dim3 grid(OUT / BN, BATCH / BM);   // (8, 64) = 512 CTAs, 2/SM
    gemm_hmma<<<grid, 256, SMEM_BYTES>>>(out);
}